// round 4
// baseline (speedup 1.0000x reference)
#include <cuda_runtime.h>
#include <cstdint>

// Problem constants (fixed by the reference):
//   x:[B=16, T=512, F=32, CI=128]  w:[F, CO=128, CI=128, K=3]  b:[F, CO]
//   y[b,t,f,o] = sum_{k,i} x[b, t-(2-k)*2, f, i] * w[f,o,i,k] + bias[f,o]
//   (taps at t-4, t-2, t; out-of-range taps are zero / causal left pad)

#define TT   512
#define FF   32
#define CIN  128
#define COUT 128

// ---- tiling ----
// CTA: 256 threads (8 warps as 4(M) x 2(N)), tile = 64 t-rows x 128 CO.
// x tile: 68 rows (t0-4 .. t0+63) so all 3 dilated taps are row offsets +0/+2/+4.
// K-dim processed in 8 chunks of 16 CI.

__device__ __forceinline__ uint32_t f2tf32(float f) {
    uint32_t r;
    asm("cvt.rna.tf32.f32 %0, %1;" : "=r"(r) : "f"(f));
    return r;
}

__global__ __launch_bounds__(256)
void TemporalConvBlock_kernel(const float* __restrict__ x,
                              const float* __restrict__ w,
                              const float* __restrict__ bias,
                              float* __restrict__ y)
{
    // A: 68 rows x 16 ci, pitch 20 (conflict-free fragment reads across groups)
    __shared__ uint32_t As[68 * 20];
    // B: 48 rows (3 taps x 16 ci) x 128 co, pitch 132 (conflict-free: (tig*4+group)%32 distinct)
    __shared__ uint32_t Bs[48 * 132];

    const int tid = threadIdx.x;
    const int t0  = blockIdx.x * 64;
    const int b   = blockIdx.y;
    const int f   = blockIdx.z;

    const int lane  = tid & 31;
    const int warp  = tid >> 5;
    const int wm    = (warp & 3) * 16;   // warp M base within tile
    const int wn    = (warp >> 2) * 64;  // warp N base within tile
    const int group = lane >> 2;         // 0..7
    const int tig   = lane & 3;          // 0..3

    const float* xbase = x + ((size_t)b * TT) * (FF * CIN) + (size_t)f * CIN;
    const float* wbase = w + (size_t)f * (COUT * CIN * 3);

    float acc[8][4];
    #pragma unroll
    for (int i = 0; i < 8; i++) {
        #pragma unroll
        for (int j = 0; j < 4; j++) acc[i][j] = 0.f;
    }

    for (int cc = 0; cc < CIN / 16; ++cc) {
        const int c0 = cc * 16;

        // ---- stage x tile: rows r=0..67 -> global t = t0-4+r; zero causal pad ----
        for (int idx = tid; idx < 68 * 16; idx += 256) {
            const int r  = idx >> 4;
            const int ci = idx & 15;
            const int t  = t0 - 4 + r;
            float v = 0.f;
            if (t >= 0) v = xbase[(size_t)t * (FF * CIN) + c0 + ci];
            As[r * 20 + ci] = f2tf32(v);
        }
        // ---- stage w tile: [3][16ci][128co]; gmem reads are coalesced over the
        //      contiguous (ci,k) inner block (j = ci*3+k, 48 consecutive floats / o) ----
        for (int idx = tid; idx < COUT * 48; idx += 256) {
            const int o  = idx / 48;
            const int j  = idx - o * 48;      // j = ci*3 + k
            const int ci = j / 3;
            const int k  = j - ci * 3;
            const float v = wbase[(size_t)o * (CIN * 3) + c0 * 3 + j];
            Bs[(k * 16 + ci) * 132 + o] = f2tf32(v);
        }
        __syncthreads();

        // ---- mma over 3 taps x 2 k-halves x 8 n-subtiles ----
        #pragma unroll
        for (int k = 0; k < 3; k++) {
            #pragma unroll
            for (int kh = 0; kh < 2; kh++) {
                const int col = kh * 8 + tig;
                const int rb  = wm + group + 2 * k;   // tap-k shifts A rows by +2k
                const uint32_t a0 = As[rb * 20 + col];
                const uint32_t a1 = As[(rb + 8) * 20 + col];
                const uint32_t a2 = As[rb * 20 + col + 4];
                const uint32_t a3 = As[(rb + 8) * 20 + col + 4];
                const uint32_t* Bk = &Bs[(k * 16 + kh * 8) * 132];
                #pragma unroll
                for (int nt = 0; nt < 8; nt++) {
                    const int n = wn + nt * 8 + group;
                    const uint32_t b0 = Bk[tig * 132 + n];
                    const uint32_t b1 = Bk[(tig + 4) * 132 + n];
                    asm volatile(
                        "mma.sync.aligned.m16n8k8.row.col.f32.tf32.tf32.f32 "
                        "{%0,%1,%2,%3}, {%4,%5,%6,%7}, {%8,%9}, {%0,%1,%2,%3};"
                        : "+f"(acc[nt][0]), "+f"(acc[nt][1]),
                          "+f"(acc[nt][2]), "+f"(acc[nt][3])
                        : "r"(a0), "r"(a1), "r"(a2), "r"(a3), "r"(b0), "r"(b1));
                }
            }
        }
        __syncthreads();
    }

    // ---- epilogue: add bias, write fp32 output (float2 stores, n even) ----
    const float* bf = bias + (size_t)f * COUT;
    const int r0 = t0 + wm + group;
    #pragma unroll
    for (int nt = 0; nt < 8; nt++) {
        const int n = wn + nt * 8 + tig * 2;
        const float b0v = bf[n];
        const float b1v = bf[n + 1];
        const size_t o0 = (((size_t)b * TT + r0) * FF + f) * (size_t)COUT + n;
        const size_t o1 = (((size_t)b * TT + r0 + 8) * FF + f) * (size_t)COUT + n;
        float2 v0 = make_float2(acc[nt][0] + b0v, acc[nt][1] + b1v);
        float2 v1 = make_float2(acc[nt][2] + b0v, acc[nt][3] + b1v);
        *reinterpret_cast<float2*>(y + o0) = v0;
        *reinterpret_cast<float2*>(y + o1) = v1;
    }
}

extern "C" void kernel_launch(void* const* d_in, const int* in_sizes, int n_in,
                              void* d_out, int out_size)
{
    const float* x    = (const float*)d_in[0];  // [16,512,32,128] fp32
    const float* w    = (const float*)d_in[1];  // [32,128,128,3]  fp32
    const float* bias = (const float*)d_in[2];  // [32,128]        fp32
    float* y = (float*)d_out;                   // [16,512,32,128] fp32

    dim3 grid(TT / 64, 16 /*B*/, FF);
    TemporalConvBlock_kernel<<<grid, 256>>>(x, w, bias, y);
}

// round 7
// speedup vs baseline: 4.2760x; 4.2760x over previous
#include <cuda_runtime.h>
#include <cstdint>

// x:[B=16, T=512, F=32, CI=128]  w:[F, CO=128, CI=128, K=3]  bias:[F, CO]
// y[b,t,f,o] = sum_{k,i} x[b, t-4+2k, f, i] * w[f,o,i,k] + bias[f,o]

#define TT   512
#define FF   32
#define CIN  128
#define COUT 128

#define PA 20            // A smem pitch (words): group*20+tig mod 32 bijective -> conflict-free
#define PB 136           // B smem pitch (words): tig*8+group mod 32 bijective -> conflict-free
#define A_WORDS (132*PA) // 132 rows (t0-4 .. t0+127) x 16 ci
#define B_WORDS (48*PB)  // 3 taps x 16 ci rows x 128 co
#define SMEM_BYTES ((2*A_WORDS + 2*B_WORDS)*4)  // 73344 B, double-buffered

// Pre-transformed weights: [f][k][ci][co], tf32 bits (cvt.rna done once here).
__device__ uint32_t g_wT[(size_t)FF * 3 * CIN * COUT];

__device__ __forceinline__ uint32_t f2tf32(float f) {
    uint32_t r;
    asm("cvt.rna.tf32.f32 %0, %1;" : "=r"(r) : "f"(f));
    return r;
}

// ---------------- prologue: w[f][o][ci][k] (fp32) -> g_wT[f][k][ci][o] (tf32) ----------------
__global__ __launch_bounds__(256)
void reformat_w_kernel(const float* __restrict__ w)
{
    __shared__ uint32_t S[16 * 385];       // [16 o][384 j], pitch 385 (conflict-free col reads)
    const int f  = blockIdx.x;             // 0..31
    const int o0 = blockIdx.y * 16;        // 0..7 -> *16
    const int warp = threadIdx.x >> 5, lane = threadIdx.x & 31;

    const float* wf = w + ((size_t)f * COUT + o0) * (CIN * 3);
    for (int oo = warp; oo < 16; oo += 8) {             // coalesced reads: 384 contiguous / row
        const float* row = wf + (size_t)oo * (CIN * 3);
        for (int j = lane; j < 384; j += 32)
            S[oo * 385 + j] = f2tf32(row[j]);
    }
    __syncthreads();

    uint32_t* out = g_wT + (size_t)f * 3 * CIN * COUT + o0;
    const int o  = threadIdx.x & 15;
    const int p0 = threadIdx.x >> 4;
    for (int p = p0; p < 384; p += 16) {                // p = k*128 + ci ; coalesced writes over o
        const int k = p >> 7, ci = p & 127;
        out[(size_t)p * COUT + o] = S[o * 385 + ci * 3 + k];
    }
}

// ---------------- cp.async helpers ----------------
__device__ __forceinline__ void cp16(uint32_t dst, const void* src, uint32_t sz) {
    asm volatile("cp.async.cg.shared.global [%0], [%1], 16, %2;\n"
                 :: "r"(dst), "l"(src), "r"(sz));
}
__device__ __forceinline__ void cp_commit() { asm volatile("cp.async.commit_group;\n"); }
template<int N> __device__ __forceinline__ void cp_wait() {
    asm volatile("cp.async.wait_group %0;\n" :: "n"(N));
}

#define MMA_TF32(d, A0,A1,A2,A3, B0,B1)                                      \
    asm volatile("mma.sync.aligned.m16n8k8.row.col.f32.tf32.tf32.f32 "       \
                 "{%0,%1,%2,%3}, {%4,%5,%6,%7}, {%8,%9}, {%0,%1,%2,%3};"     \
                 : "+f"((d)[0]), "+f"((d)[1]), "+f"((d)[2]), "+f"((d)[3])    \
                 : "r"(A0), "r"(A1), "r"(A2), "r"(A3), "r"(B0), "r"(B1))

// ---------------- main kernel ----------------
// CTA: 256 thr (8 warps as 4M x 2N), tile = 128 t-rows x 128 co; warp = 32M x 64N.
// K processed in 8 chunks of 16 ci; x tile rows t0-4..t0+127 so taps are row offsets +0/+2/+4.
__global__ __launch_bounds__(256, 2)
void conv_mma_kernel(const float* __restrict__ x,
                     const float* __restrict__ bias,
                     float* __restrict__ y)
{
    extern __shared__ uint32_t smem[];   // [A0 | A1 | B0 | B1]
    const int tid  = threadIdx.x;
    const int t0   = blockIdx.x * 128;
    const int b    = blockIdx.y;
    const int f    = blockIdx.z;
    const int lane = tid & 31, warp = tid >> 5;
    const int wm   = (warp & 3) * 32;
    const int wn   = (warp >> 2) * 64;
    const int group = lane >> 2;   // 0..7
    const int tig   = lane & 3;    // 0..3

    const uint32_t sbase = (uint32_t)__cvta_generic_to_shared(smem);

    // --- per-thread staging plan (computed once; per chunk only a constant offset is added) ---
    // A: 132 rows x 16 ci = 132*64B = 528 x 16B chunks; t<0 -> zero-fill via src-size 0
    const char* xrow0 = (const char*)(x + ((size_t)b * TT) * (FF * CIN) + (size_t)f * CIN);
    uint32_t a_dst[3], a_off[3], a_sz[3];
    int a_cnt = 0;
    for (int i = tid; i < 528; i += 256) {
        const int r = i >> 2, seg = i & 3;
        const int t = t0 - 4 + r;
        a_dst[a_cnt] = (uint32_t)((r * PA + seg * 4) * 4);
        a_off[a_cnt] = (uint32_t)((t < 0 ? 0 : t) * (FF * CIN) * 4 + seg * 16);
        a_sz[a_cnt]  = (t >= 0) ? 16u : 0u;
        a_cnt++;
    }
    // B: 48 rows x 128 co = 48*512B = 1536 x 16B chunks, exactly 6/thread, fully coalesced
    const char* wfT = (const char*)(g_wT + (size_t)f * 3 * CIN * COUT);
    uint32_t b_dst[6], b_off[6];
    #pragma unroll
    for (int j = 0; j < 6; j++) {
        const int i = tid + j * 256;
        const int row = i >> 5, seg = i & 31;
        b_dst[j] = (uint32_t)((row * PB + seg * 4) * 4);
        const int k = row >> 4, ci = row & 15;
        b_off[j] = (uint32_t)((k * CIN * COUT + ci * COUT + seg * 4) * 4);
    }

    auto prefetch = [&](int cc, int d) {
        const uint32_t aB = sbase + (uint32_t)(d * A_WORDS * 4);
        const uint32_t bB = sbase + (uint32_t)((2 * A_WORDS + d * B_WORDS) * 4);
        const uint32_t cA = (uint32_t)(cc * 16 * 4);          // c0 * 4 bytes into ci
        const uint32_t cB = (uint32_t)(cc * 16 * COUT * 4);   // c0 * COUT words
        for (int j = 0; j < a_cnt; j++)
            cp16(aB + a_dst[j], xrow0 + a_off[j] + cA, a_sz[j]);
        #pragma unroll
        for (int j = 0; j < 6; j++)
            cp16(bB + b_dst[j], wfT + b_off[j] + cB, 16u);
    };

    float acc[2][8][4];
    #pragma unroll
    for (int i = 0; i < 2; i++)
        #pragma unroll
        for (int j = 0; j < 8; j++)
            #pragma unroll
            for (int q = 0; q < 4; q++) acc[i][j][q] = 0.f;

    prefetch(0, 0);
    cp_commit();

    const uint32_t* Ath0 = smem + (wm + group) * PA + tig;
    const uint32_t* Bth0 = smem + 2 * A_WORDS + tig * PB + wn + group;

    #pragma unroll 1
    for (int cc = 0; cc < 8; ++cc) {
        const int d = cc & 1;
        if (cc < 7) { prefetch(cc + 1, d ^ 1); cp_commit(); }
        if (cc < 7) cp_wait<1>(); else cp_wait<0>();
        __syncthreads();

        const uint32_t* Ath = Ath0 + d * A_WORDS;
        const uint32_t* Bth = Bth0 + d * B_WORDS;

        #pragma unroll
        for (int k = 0; k < 3; k++) {        // taps: A rows shift by +2 per tap
            #pragma unroll
            for (int kh = 0; kh < 2; kh++) { // two K=8 halves of the 16-ci chunk
                const uint32_t* Ap = Ath + (2 * k) * PA + kh * 8;
                const uint32_t a0 = Ap[0],         a1 = Ap[8 * PA];
                const uint32_t a2 = Ap[4],         a3 = Ap[8 * PA + 4];
                const uint32_t a4 = Ap[16 * PA],   a5 = Ap[24 * PA];
                const uint32_t a6 = Ap[16 * PA + 4], a7 = Ap[24 * PA + 4];
                const uint32_t* Bp = Bth + (k * 16 + kh * 8) * PB;
                #pragma unroll
                for (int nt = 0; nt < 8; nt++) {
                    const uint32_t b0v = Bp[nt * 8];
                    const uint32_t b1v = Bp[4 * PB + nt * 8];
                    MMA_TF32(acc[0][nt], a0, a1, a2, a3, b0v, b1v);  // M rows wm..wm+15
                    MMA_TF32(acc[1][nt], a4, a5, a6, a7, b0v, b1v);  // M rows wm+16..wm+31
                }
            }
        }
        __syncthreads();
    }

    // --- epilogue: bias + fp32 stores (float2) ---
    const float* bf = bias + (size_t)f * COUT;
    const int r0 = t0 + wm + group;
    #pragma unroll
    for (int nt = 0; nt < 8; nt++) {
        const int n = wn + nt * 8 + tig * 2;
        const float bx = bf[n], by = bf[n + 1];
        #pragma unroll
        for (int rb = 0; rb < 2; rb++) {
            const int r = r0 + rb * 16;
            const size_t o0i = (((size_t)b * TT + r) * FF + f) * (size_t)COUT + n;
            const size_t o1i = (((size_t)b * TT + r + 8) * FF + f) * (size_t)COUT + n;
            *reinterpret_cast<float2*>(y + o0i) =
                make_float2(acc[rb][nt][0] + bx, acc[rb][nt][1] + by);
            *reinterpret_cast<float2*>(y + o1i) =
                make_float2(acc[rb][nt][2] + bx, acc[rb][nt][3] + by);
        }
    }
}

extern "C" void kernel_launch(void* const* d_in, const int* in_sizes, int n_in,
                              void* d_out, int out_size)
{
    const float* x    = (const float*)d_in[0];  // [16,512,32,128]
    const float* w    = (const float*)d_in[1];  // [32,128,128,3]
    const float* bias = (const float*)d_in[2];  // [32,128]
    float* y = (float*)d_out;

    cudaFuncSetAttribute(conv_mma_kernel,
                         cudaFuncAttributeMaxDynamicSharedMemorySize, SMEM_BYTES);

    dim3 gridW(FF, 8);
    reformat_w_kernel<<<gridW, 256>>>(w);

    dim3 grid(TT / 128, 16 /*B*/, FF);
    conv_mma_kernel<<<grid, 256, SMEM_BYTES>>>(x, bias, y);
}